// round 1
// baseline (speedup 1.0000x reference)
#include <cuda_runtime.h>
#include <math.h>

#define BB 1024
#define HH 1024
#define DD 512
#define PP 66
#define TIN 10
#define TOUT 25
#define GG 4096   // 4*HH

// ---------------- static device scratch (no allocations allowed) ----------------
__device__ float d_WcombX[GG * PP];
__device__ float d_WcombZ[GG * PP];
__device__ float d_bcombX[GG];
__device__ float d_bcombZ[GG];
__device__ float d_Wcat[(size_t)GG * 2048];          // [4096][2048]: cols 0..1023 = dec_whh, 1024..2047 = dec_wih@lin_w
__device__ float d_bcat[GG];
__device__ float d_ginX[(size_t)TIN * BB * GG];      // precomputed input gates (incl. all biases)
__device__ float d_ginZ[(size_t)TIN * BB * GG];
__device__ float d_allh[(size_t)TIN * BB * HH];
__device__ float d_allhz[(size_t)TIN * BB * HH];
__device__ float d_cX[BB * HH];
__device__ float d_cZ[BB * HH];
__device__ float d_decc[BB * HH];
__device__ float d_gates[(size_t)2 * BB * GG];
__device__ float d_hcat[(size_t)BB * 2048];          // [atth | h_n]
__device__ float d_dechs[(size_t)TOUT * BB * HH];

// ---------------- generic tiled SGEMM ----------------
struct GP {
    const float* A;
    const float* Bm;
    float* C;
    const float* ep;     // bias [N] or preadd matrix [M,N]
    int M, N, K, lda, ldc, ldep;
};

enum { A_PLAIN = 0, A_XG = 1, A_PG = 2 };   // A gather modes
enum { B_NK = 0, B_KN = 1 };                // B layout: [N,K] (use B^T) or [K,N]
enum { E_NONE = 0, E_BIAS = 1, E_PRE = 2 }; // epilogue

template <int AMAP, int BMODE, int EPI>
__global__ __launch_bounds__(256) void sgemm_k(GP p0, GP p1) {
    GP p = (blockIdx.z == 0) ? p0 : p1;
    __shared__ float As[8][128];
    __shared__ float Bs[8][128];
    const int tid = threadIdx.x;
    const int tx = tid & 15, ty = tid >> 4;
    const int m0 = blockIdx.x * 128, n0 = blockIdx.y * 128;

    float acc[8][8];
#pragma unroll
    for (int i = 0; i < 8; i++)
#pragma unroll
        for (int j = 0; j < 8; j++) acc[i][j] = 0.f;

    const int kl = tid & 7;    // k within tile
    const int rl = tid >> 3;   // row/col base 0..31

    for (int k0 = 0; k0 < p.K; k0 += 8) {
        __syncthreads();
        // ---- load A tile (As[k][m]) ----
#pragma unroll
        for (int i = 0; i < 4; i++) {
            int m = rl + 32 * i;
            int gm = m0 + m, gk = k0 + kl;
            float v = 0.f;
            if (gm < p.M && gk < p.K) {
                size_t off;
                if (AMAP == A_PLAIN) {
                    off = (size_t)gm * p.lda + gk;
                } else if (AMAP == A_XG) {   // row (t*BB+b) -> x[b, t, k]
                    int t = gm / BB, b = gm % BB;
                    off = (size_t)b * (TIN * PP) + (size_t)t * PP + gk;
                } else {                     // row (b*TOUT+t) -> dechs[t, b, k]
                    int b = gm / TOUT, t = gm % TOUT;
                    off = (size_t)t * BB * HH + (size_t)b * HH + gk;
                }
                v = p.A[off];
            }
            As[kl][m] = v;
        }
        // ---- load B tile (Bs[k][n]) ----
        if (BMODE == B_NK) {
#pragma unroll
            for (int i = 0; i < 4; i++) {
                int n = rl + 32 * i;
                int gn = n0 + n, gk = k0 + kl;
                float v = 0.f;
                if (gn < p.N && gk < p.K) v = p.Bm[(size_t)gn * p.K + gk];
                Bs[kl][n] = v;
            }
        } else {
            int nb = tid & 127, kb = tid >> 7;
#pragma unroll
            for (int i = 0; i < 4; i++) {
                int kk = kb + 2 * i;
                int gn = n0 + nb, gk = k0 + kk;
                float v = 0.f;
                if (gn < p.N && gk < p.K) v = p.Bm[(size_t)gk * p.N + gn];
                Bs[kk][nb] = v;
            }
        }
        __syncthreads();
        // ---- compute ----
#pragma unroll
        for (int kk = 0; kk < 8; kk++) {
            float a[8], b[8];
#pragma unroll
            for (int i = 0; i < 8; i++) a[i] = As[kk][ty * 8 + i];
#pragma unroll
            for (int j = 0; j < 8; j++) b[j] = Bs[kk][tx * 8 + j];
#pragma unroll
            for (int i = 0; i < 8; i++)
#pragma unroll
                for (int j = 0; j < 8; j++) acc[i][j] += a[i] * b[j];
        }
    }
    // ---- epilogue ----
#pragma unroll
    for (int i = 0; i < 8; i++) {
        int gm = m0 + ty * 8 + i;
        if (gm >= p.M) continue;
#pragma unroll
        for (int j = 0; j < 8; j++) {
            int gn = n0 + tx * 8 + j;
            if (gn >= p.N) continue;
            float v = acc[i][j];
            if (EPI == E_BIAS) v += p.ep[gn];
            if (EPI == E_PRE) v += p.ep[(size_t)gm * p.ldep + gn];
            p.C[(size_t)gm * p.ldc + gn] = v;
        }
    }
}

// ---------------- LSTM pointwise cell ----------------
__global__ void lstm_cell_k(const float* __restrict__ gates, const float* __restrict__ cprev,
                            float* __restrict__ cout, float* __restrict__ hout, int first) {
    int idx = blockIdx.x * blockDim.x + threadIdx.x;
    if (idx >= BB * HH) return;
    int b = idx >> 10, u = idx & 1023;
    const float* g = gates + (size_t)b * GG;
    float gi = g[u], gf = g[HH + u], gc = g[2 * HH + u], go = g[3 * HH + u];
    float c = first ? 0.f : cprev[idx];
    float si = 1.f / (1.f + expf(-gi));
    float sf = 1.f / (1.f + expf(-gf));
    float so = 1.f / (1.f + expf(-go));
    float cn = sf * c + si * tanhf(gc);
    cout[idx] = cn;
    hout[idx] = so * tanhf(cn);
}

// ---------------- attention (one block per batch row) ----------------
__global__ void attention_k(const float* __restrict__ allh, const float* __restrict__ allhz,
                            const float* __restrict__ hprev, const float* __restrict__ cvec,
                            float* __restrict__ hcat) {
    int b = blockIdx.x;
    int tid = threadIdx.x, lane = tid & 31, w = tid >> 5;  // 8 warps
    __shared__ float sc[21];
    __shared__ float wts[21];
    const float* cb = cvec + (size_t)b * HH;

    for (int s = w; s < 21; s += 8) {
        const float* hs = (s < TIN)  ? (allh + ((size_t)s * BB + b) * HH)
                        : (s == TIN) ? (hprev + (size_t)b * HH)
                                     : (allhz + ((size_t)(s - TIN - 1) * BB + b) * HH);
        float part = 0.f;
        for (int u = lane; u < HH; u += 32) part += hs[u] * cb[u];
#pragma unroll
        for (int off = 16; off; off >>= 1) part += __shfl_down_sync(0xffffffffu, part, off);
        if (lane == 0) sc[s] = part;
    }
    __syncthreads();
    if (tid == 0) {
        float mx = sc[0];
        for (int s = 1; s < 21; s++) mx = fmaxf(mx, sc[s]);
        float sum = 0.f;
        for (int s = 0; s < 21; s++) { float e = expf(sc[s] - mx); wts[s] = e; sum += e; }
        float inv = 1.f / sum;
        for (int s = 0; s < 21; s++) wts[s] *= inv;
    }
    __syncthreads();
    float* out = hcat + (size_t)b * 2048;
    for (int u = tid; u < HH; u += blockDim.x) {
        float accv = 0.f;
#pragma unroll
        for (int s = 0; s < 21; s++) {
            const float* hs = (s < TIN)  ? (allh + ((size_t)s * BB + b) * HH)
                            : (s == TIN) ? (hprev + (size_t)b * HH)
                                         : (allhz + ((size_t)(s - TIN - 1) * BB + b) * HH);
            accv += wts[s] * hs[u];
        }
        out[u] = accv;                                   // new "h" into the cell = atth
        out[HH + u] = hprev[(size_t)b * HH + u];         // h_n for the folded lin path
    }
}

// ---------------- bias folding: out[j] = b1[j] + b2[j] + dot(wih[j,:], vec) ----------------
__global__ void prep_bias_k(const float* __restrict__ wih, const float* __restrict__ vec,
                            const float* __restrict__ b1, const float* __restrict__ b2,
                            float* __restrict__ out) {
    int wid = (blockIdx.x * blockDim.x + threadIdx.x) >> 5;
    int lane = threadIdx.x & 31;
    if (wid >= GG) return;
    const float* row = wih + (size_t)wid * DD;
    float s = 0.f;
    for (int d = lane; d < DD; d += 32) s += row[d] * vec[d];
#pragma unroll
    for (int off = 16; off; off >>= 1) s += __shfl_down_sync(0xffffffffu, s, off);
    if (lane == 0) out[wid] = b1[wid] + b2[wid] + s;
}

// copy dec_whh into left half of Wcat
__global__ void pack_wcat_k(const float* __restrict__ whh) {
    size_t idx = (size_t)blockIdx.x * blockDim.x + threadIdx.x;
    if (idx >= (size_t)GG * HH) return;
    size_t j = idx >> 10, m = idx & 1023;
    d_Wcat[j * 2048 + m] = whh[idx];
}

// ---------------- host orchestration ----------------
extern "C" void kernel_launch(void* const* d_in, const int* in_sizes, int n_in,
                              void* d_out, int out_size) {
    const float* x        = (const float*)d_in[0];
    const float* z        = (const float*)d_in[1];
    const float* wf       = (const float*)d_in[2];
    const float* bf       = (const float*)d_in[3];
    const float* enc_wih  = (const float*)d_in[4];
    const float* enc_whh  = (const float*)d_in[5];
    const float* enc_bih  = (const float*)d_in[6];
    const float* enc_bhh  = (const float*)d_in[7];
    const float* encp_wih = (const float*)d_in[8];
    const float* encp_whh = (const float*)d_in[9];
    const float* encp_bih = (const float*)d_in[10];
    const float* encp_bhh = (const float*)d_in[11];
    const float* dec_wih  = (const float*)d_in[12];
    const float* dec_whh  = (const float*)d_in[13];
    const float* dec_bih  = (const float*)d_in[14];
    const float* dec_bhh  = (const float*)d_in[15];
    const float* lin_w    = (const float*)d_in[16];
    const float* lin_b    = (const float*)d_in[17];
    const float* pose_w   = (const float*)d_in[18];
    const float* pose_b   = (const float*)d_in[19];
    float* out = (float*)d_out;

    void* pv;
    cudaGetSymbolAddress(&pv, d_WcombX); float* WcombX = (float*)pv;
    cudaGetSymbolAddress(&pv, d_WcombZ); float* WcombZ = (float*)pv;
    cudaGetSymbolAddress(&pv, d_bcombX); float* bcombX = (float*)pv;
    cudaGetSymbolAddress(&pv, d_bcombZ); float* bcombZ = (float*)pv;
    cudaGetSymbolAddress(&pv, d_Wcat);   float* Wcat   = (float*)pv;
    cudaGetSymbolAddress(&pv, d_bcat);   float* bcat   = (float*)pv;
    cudaGetSymbolAddress(&pv, d_ginX);   float* ginX   = (float*)pv;
    cudaGetSymbolAddress(&pv, d_ginZ);   float* ginZ   = (float*)pv;
    cudaGetSymbolAddress(&pv, d_allh);   float* allh   = (float*)pv;
    cudaGetSymbolAddress(&pv, d_allhz);  float* allhz  = (float*)pv;
    cudaGetSymbolAddress(&pv, d_cX);     float* cX     = (float*)pv;
    cudaGetSymbolAddress(&pv, d_cZ);     float* cZ     = (float*)pv;
    cudaGetSymbolAddress(&pv, d_decc);   float* decc   = (float*)pv;
    cudaGetSymbolAddress(&pv, d_gates);  float* gates  = (float*)pv;
    cudaGetSymbolAddress(&pv, d_hcat);   float* hcat   = (float*)pv;
    cudaGetSymbolAddress(&pv, d_dechs);  float* dechs  = (float*)pv;

    // ---- one-time folds (cheap, fully parallel) ----
    pack_wcat_k<<<(GG * HH + 255) / 256, 256>>>(dec_whh);
    prep_bias_k<<<512, 256>>>(enc_wih, bf, enc_bih, enc_bhh, bcombX);
    prep_bias_k<<<512, 256>>>(encp_wih, bf, encp_bih, encp_bhh, bcombZ);
    prep_bias_k<<<512, 256>>>(dec_wih, lin_b, dec_bih, dec_bhh, bcat);

    {   // Wcomb = enc_wih @ wf  (both encoders via z)
        GP p0 = {enc_wih,  wf, WcombX, nullptr, GG, PP, DD, DD, PP, 0};
        GP p1 = {encp_wih, wf, WcombZ, nullptr, GG, PP, DD, DD, PP, 0};
        dim3 g((GG + 127) / 128, 1, 2);
        sgemm_k<A_PLAIN, B_KN, E_NONE><<<g, 256>>>(p0, p1);
    }
    {   // Weff = dec_wih @ lin_w into right half of Wcat
        GP p0 = {dec_wih, lin_w, Wcat + 1024, nullptr, GG, HH, DD, DD, 2048, 0};
        dim3 g((GG + 127) / 128, (HH + 127) / 128, 1);
        sgemm_k<A_PLAIN, B_KN, E_NONE><<<g, 256>>>(p0, p0);
    }
    {   // input gates for all timesteps: gin[t,b,:] = x[b,t,:] @ Wcomb^T + bcomb
        GP p0 = {x, WcombX, ginX, bcombX, TIN * BB, GG, PP, PP, GG, 0};
        GP p1 = {z, WcombZ, ginZ, bcombZ, TIN * BB, GG, PP, PP, GG, 0};
        dim3 g((TIN * BB + 127) / 128, GG / 128, 2);
        sgemm_k<A_XG, B_NK, E_BIAS><<<g, 256>>>(p0, p1);
    }

    // ---- encoder recurrence (t=0 needs no GEMM: h0 = 0) ----
    lstm_cell_k<<<4096, 256>>>(ginX, cX, cX, allh, 1);
    lstm_cell_k<<<4096, 256>>>(ginZ, cZ, cZ, allhz, 1);
    for (int t = 1; t < TIN; t++) {
        GP p0 = {allh  + (size_t)(t - 1) * BB * HH, enc_whh,  gates,
                 ginX + (size_t)t * BB * GG, BB, GG, HH, HH, GG, GG};
        GP p1 = {allhz + (size_t)(t - 1) * BB * HH, encp_whh, gates + (size_t)BB * GG,
                 ginZ + (size_t)t * BB * GG, BB, GG, HH, HH, GG, GG};
        dim3 g(BB / 128, GG / 128, 2);
        sgemm_k<A_PLAIN, B_NK, E_PRE><<<g, 256>>>(p0, p1);
        lstm_cell_k<<<4096, 256>>>(gates, cX, cX, allh + (size_t)t * BB * HH, 0);
        lstm_cell_k<<<4096, 256>>>(gates + (size_t)BB * GG, cZ, cZ, allhz + (size_t)t * BB * HH, 0);
    }

    // ---- decoder ----
    for (int t = 0; t < TOUT; t++) {
        const float* hprev = (t == 0) ? (allh + (size_t)(TIN - 1) * BB * HH)
                                      : (dechs + (size_t)(t - 1) * BB * HH);
        const float* cptr = (t == 0) ? cX : decc;
        attention_k<<<BB, 256>>>(allh, allhz, hprev, cptr, hcat);
        GP p0 = {hcat, Wcat, gates, bcat, BB, GG, 2048, 2048, GG, 0};
        dim3 g(BB / 128, GG / 128, 1);
        sgemm_k<A_PLAIN, B_NK, E_BIAS><<<g, 256>>>(p0, p0);
        lstm_cell_k<<<4096, 256>>>(gates, cptr, decc, dechs + (size_t)t * BB * HH, 0);
    }

    // ---- output projection: out[b,t,:] = dechs[t,b,:] @ pose_w^T + pose_b ----
    {
        GP p0 = {dechs, pose_w, out, pose_b, BB * TOUT, PP, HH, HH, PP, 0};
        dim3 g((BB * TOUT + 127) / 128, 1, 1);
        sgemm_k<A_PG, B_NK, E_BIAS><<<g, 256>>>(p0, p0);
    }
}

// round 2
// speedup vs baseline: 1.0034x; 1.0034x over previous
#include <cuda_runtime.h>
#include <math.h>

#define BB 1024
#define HH 1024
#define DD 512
#define PP 66
#define TIN 10
#define TOUT 25
#define GG 4096   // 4*HH

// ---------------- static device scratch (no allocations allowed) ----------------
__device__ float d_WcombX[GG * PP];
__device__ float d_WcombZ[GG * PP];
__device__ float d_bcombX[GG];
__device__ float d_bcombZ[GG];
__device__ float d_Wcat[(size_t)GG * 2048];          // [4096][2048]: cols 0..1023 = dec_whh, 1024..2047 = dec_wih@lin_w
__device__ float d_bcat[GG];
__device__ float d_ginX[(size_t)TIN * BB * GG];      // precomputed input gates (incl. all biases)
__device__ float d_ginZ[(size_t)TIN * BB * GG];
__device__ float d_allh[(size_t)TIN * BB * HH];
__device__ float d_allhz[(size_t)TIN * BB * HH];
__device__ float d_cX[BB * HH];
__device__ float d_cZ[BB * HH];
__device__ float d_decc[BB * HH];
__device__ float d_gates[(size_t)2 * BB * GG];
__device__ float d_hcat[(size_t)BB * 2048];          // [atth | h_n]
__device__ float d_dechs[(size_t)TOUT * BB * HH];

// ---------------- generic tiled SGEMM ----------------
struct GP {
    const float* A;
    const float* Bm;
    float* C;
    const float* ep;     // bias [N] or preadd matrix [M,N]
    int M, N, K, lda, ldc, ldep;
};

enum { A_PLAIN = 0, A_XG = 1, A_PG = 2 };   // A gather modes
enum { B_NK = 0, B_KN = 1 };                // B layout: [N,K] (use B^T) or [K,N]
enum { E_NONE = 0, E_BIAS = 1, E_PRE = 2 }; // epilogue

template <int AMAP, int BMODE, int EPI>
__global__ __launch_bounds__(256) void sgemm_k(GP p0, GP p1) {
    GP p = (blockIdx.z == 0) ? p0 : p1;
    __shared__ float As[8][128];
    __shared__ float Bs[8][128];
    const int tid = threadIdx.x;
    const int tx = tid & 15, ty = tid >> 4;
    const int m0 = blockIdx.x * 128, n0 = blockIdx.y * 128;

    float acc[8][8];
#pragma unroll
    for (int i = 0; i < 8; i++)
#pragma unroll
        for (int j = 0; j < 8; j++) acc[i][j] = 0.f;

    const int kl = tid & 7;    // k within tile
    const int rl = tid >> 3;   // row/col base 0..31

    for (int k0 = 0; k0 < p.K; k0 += 8) {
        __syncthreads();
        // ---- load A tile (As[k][m]) ----
#pragma unroll
        for (int i = 0; i < 4; i++) {
            int m = rl + 32 * i;
            int gm = m0 + m, gk = k0 + kl;
            float v = 0.f;
            if (gm < p.M && gk < p.K) {
                size_t off;
                if (AMAP == A_PLAIN) {
                    off = (size_t)gm * p.lda + gk;
                } else if (AMAP == A_XG) {   // row (t*BB+b) -> x[b, t, k]
                    int t = gm / BB, b = gm % BB;
                    off = (size_t)b * (TIN * PP) + (size_t)t * PP + gk;
                } else {                     // row (b*TOUT+t) -> dechs[t, b, k]
                    int b = gm / TOUT, t = gm % TOUT;
                    off = (size_t)t * BB * HH + (size_t)b * HH + gk;
                }
                v = p.A[off];
            }
            As[kl][m] = v;
        }
        // ---- load B tile (Bs[k][n]) ----
        if (BMODE == B_NK) {
#pragma unroll
            for (int i = 0; i < 4; i++) {
                int n = rl + 32 * i;
                int gn = n0 + n, gk = k0 + kl;
                float v = 0.f;
                if (gn < p.N && gk < p.K) v = p.Bm[(size_t)gn * p.K + gk];
                Bs[kl][n] = v;
            }
        } else {
            int nb = tid & 127, kb = tid >> 7;
#pragma unroll
            for (int i = 0; i < 4; i++) {
                int kk = kb + 2 * i;
                int gn = n0 + nb, gk = k0 + kk;
                float v = 0.f;
                if (gn < p.N && gk < p.K) v = p.Bm[(size_t)gk * p.N + gn];
                Bs[kk][nb] = v;
            }
        }
        __syncthreads();
        // ---- compute ----
#pragma unroll
        for (int kk = 0; kk < 8; kk++) {
            float a[8], b[8];
#pragma unroll
            for (int i = 0; i < 8; i++) a[i] = As[kk][ty * 8 + i];
#pragma unroll
            for (int j = 0; j < 8; j++) b[j] = Bs[kk][tx * 8 + j];
#pragma unroll
            for (int i = 0; i < 8; i++)
#pragma unroll
                for (int j = 0; j < 8; j++) acc[i][j] += a[i] * b[j];
        }
    }
    // ---- epilogue ----
#pragma unroll
    for (int i = 0; i < 8; i++) {
        int gm = m0 + ty * 8 + i;
        if (gm >= p.M) continue;
#pragma unroll
        for (int j = 0; j < 8; j++) {
            int gn = n0 + tx * 8 + j;
            if (gn >= p.N) continue;
            float v = acc[i][j];
            if (EPI == E_BIAS) v += p.ep[gn];
            if (EPI == E_PRE) v += p.ep[(size_t)gm * p.ldep + gn];
            p.C[(size_t)gm * p.ldc + gn] = v;
        }
    }
}

// ---------------- LSTM pointwise cell ----------------
__global__ void lstm_cell_k(const float* __restrict__ gates, const float* __restrict__ cprev,
                            float* __restrict__ cout, float* __restrict__ hout, int first) {
    int idx = blockIdx.x * blockDim.x + threadIdx.x;
    if (idx >= BB * HH) return;
    int b = idx >> 10, u = idx & 1023;
    const float* g = gates + (size_t)b * GG;
    float gi = g[u], gf = g[HH + u], gc = g[2 * HH + u], go = g[3 * HH + u];
    float c = first ? 0.f : cprev[idx];
    float si = 1.f / (1.f + expf(-gi));
    float sf = 1.f / (1.f + expf(-gf));
    float so = 1.f / (1.f + expf(-go));
    float cn = sf * c + si * tanhf(gc);
    cout[idx] = cn;
    hout[idx] = so * tanhf(cn);
}

// ---------------- attention (one block per batch row) ----------------
__global__ void attention_k(const float* __restrict__ allh, const float* __restrict__ allhz,
                            const float* __restrict__ hprev, const float* __restrict__ cvec,
                            float* __restrict__ hcat) {
    int b = blockIdx.x;
    int tid = threadIdx.x, lane = tid & 31, w = tid >> 5;  // 8 warps
    __shared__ float sc[21];
    __shared__ float wts[21];
    const float* cb = cvec + (size_t)b * HH;

    for (int s = w; s < 21; s += 8) {
        const float* hs = (s < TIN)  ? (allh + ((size_t)s * BB + b) * HH)
                        : (s == TIN) ? (hprev + (size_t)b * HH)
                                     : (allhz + ((size_t)(s - TIN - 1) * BB + b) * HH);
        float part = 0.f;
        for (int u = lane; u < HH; u += 32) part += hs[u] * cb[u];
#pragma unroll
        for (int off = 16; off; off >>= 1) part += __shfl_down_sync(0xffffffffu, part, off);
        if (lane == 0) sc[s] = part;
    }
    __syncthreads();
    if (tid == 0) {
        float mx = sc[0];
        for (int s = 1; s < 21; s++) mx = fmaxf(mx, sc[s]);
        float sum = 0.f;
        for (int s = 0; s < 21; s++) { float e = expf(sc[s] - mx); wts[s] = e; sum += e; }
        float inv = 1.f / sum;
        for (int s = 0; s < 21; s++) wts[s] *= inv;
    }
    __syncthreads();
    float* out = hcat + (size_t)b * 2048;
    for (int u = tid; u < HH; u += blockDim.x) {
        float accv = 0.f;
#pragma unroll
        for (int s = 0; s < 21; s++) {
            const float* hs = (s < TIN)  ? (allh + ((size_t)s * BB + b) * HH)
                            : (s == TIN) ? (hprev + (size_t)b * HH)
                                         : (allhz + ((size_t)(s - TIN - 1) * BB + b) * HH);
            accv += wts[s] * hs[u];
        }
        out[u] = accv;                                   // new "h" into the cell = atth
        out[HH + u] = hprev[(size_t)b * HH + u];         // h_n for the folded lin path
    }
}

// ---------------- bias folding: out[j] = b1[j] + b2[j] + dot(wih[j,:], vec) ----------------
__global__ void prep_bias_k(const float* __restrict__ wih, const float* __restrict__ vec,
                            const float* __restrict__ b1, const float* __restrict__ b2,
                            float* __restrict__ out) {
    int wid = (blockIdx.x * blockDim.x + threadIdx.x) >> 5;
    int lane = threadIdx.x & 31;
    if (wid >= GG) return;
    const float* row = wih + (size_t)wid * DD;
    float s = 0.f;
    for (int d = lane; d < DD; d += 32) s += row[d] * vec[d];
#pragma unroll
    for (int off = 16; off; off >>= 1) s += __shfl_down_sync(0xffffffffu, s, off);
    if (lane == 0) out[wid] = b1[wid] + b2[wid] + s;
}

// copy dec_whh into left half of Wcat
__global__ void pack_wcat_k(const float* __restrict__ whh) {
    size_t idx = (size_t)blockIdx.x * blockDim.x + threadIdx.x;
    if (idx >= (size_t)GG * HH) return;
    size_t j = idx >> 10, m = idx & 1023;
    d_Wcat[j * 2048 + m] = whh[idx];
}

// ---------------- host orchestration ----------------
extern "C" void kernel_launch(void* const* d_in, const int* in_sizes, int n_in,
                              void* d_out, int out_size) {
    const float* x        = (const float*)d_in[0];
    const float* z        = (const float*)d_in[1];
    const float* wf       = (const float*)d_in[2];
    const float* bf       = (const float*)d_in[3];
    const float* enc_wih  = (const float*)d_in[4];
    const float* enc_whh  = (const float*)d_in[5];
    const float* enc_bih  = (const float*)d_in[6];
    const float* enc_bhh  = (const float*)d_in[7];
    const float* encp_wih = (const float*)d_in[8];
    const float* encp_whh = (const float*)d_in[9];
    const float* encp_bih = (const float*)d_in[10];
    const float* encp_bhh = (const float*)d_in[11];
    const float* dec_wih  = (const float*)d_in[12];
    const float* dec_whh  = (const float*)d_in[13];
    const float* dec_bih  = (const float*)d_in[14];
    const float* dec_bhh  = (const float*)d_in[15];
    const float* lin_w    = (const float*)d_in[16];
    const float* lin_b    = (const float*)d_in[17];
    const float* pose_w   = (const float*)d_in[18];
    const float* pose_b   = (const float*)d_in[19];
    float* out = (float*)d_out;

    void* pv;
    cudaGetSymbolAddress(&pv, d_WcombX); float* WcombX = (float*)pv;
    cudaGetSymbolAddress(&pv, d_WcombZ); float* WcombZ = (float*)pv;
    cudaGetSymbolAddress(&pv, d_bcombX); float* bcombX = (float*)pv;
    cudaGetSymbolAddress(&pv, d_bcombZ); float* bcombZ = (float*)pv;
    cudaGetSymbolAddress(&pv, d_Wcat);   float* Wcat   = (float*)pv;
    cudaGetSymbolAddress(&pv, d_bcat);   float* bcat   = (float*)pv;
    cudaGetSymbolAddress(&pv, d_ginX);   float* ginX   = (float*)pv;
    cudaGetSymbolAddress(&pv, d_ginZ);   float* ginZ   = (float*)pv;
    cudaGetSymbolAddress(&pv, d_allh);   float* allh   = (float*)pv;
    cudaGetSymbolAddress(&pv, d_allhz);  float* allhz  = (float*)pv;
    cudaGetSymbolAddress(&pv, d_cX);     float* cX     = (float*)pv;
    cudaGetSymbolAddress(&pv, d_cZ);     float* cZ     = (float*)pv;
    cudaGetSymbolAddress(&pv, d_decc);   float* decc   = (float*)pv;
    cudaGetSymbolAddress(&pv, d_gates);  float* gates  = (float*)pv;
    cudaGetSymbolAddress(&pv, d_hcat);   float* hcat   = (float*)pv;
    cudaGetSymbolAddress(&pv, d_dechs);  float* dechs  = (float*)pv;

    // ---- one-time folds (cheap, fully parallel) ----
    pack_wcat_k<<<(GG * HH + 255) / 256, 256>>>(dec_whh);
    prep_bias_k<<<512, 256>>>(enc_wih, bf, enc_bih, enc_bhh, bcombX);
    prep_bias_k<<<512, 256>>>(encp_wih, bf, encp_bih, encp_bhh, bcombZ);
    prep_bias_k<<<512, 256>>>(dec_wih, lin_b, dec_bih, dec_bhh, bcat);

    {   // Wcomb = enc_wih @ wf  (both encoders via z)
        GP p0 = {enc_wih,  wf, WcombX, nullptr, GG, PP, DD, DD, PP, 0};
        GP p1 = {encp_wih, wf, WcombZ, nullptr, GG, PP, DD, DD, PP, 0};
        dim3 g((GG + 127) / 128, 1, 2);
        sgemm_k<A_PLAIN, B_KN, E_NONE><<<g, 256>>>(p0, p1);
    }
    {   // Weff = dec_wih @ lin_w into right half of Wcat
        GP p0 = {dec_wih, lin_w, Wcat + 1024, nullptr, GG, HH, DD, DD, 2048, 0};
        dim3 g((GG + 127) / 128, (HH + 127) / 128, 1);
        sgemm_k<A_PLAIN, B_KN, E_NONE><<<g, 256>>>(p0, p0);
    }
    {   // input gates for all timesteps: gin[t,b,:] = x[b,t,:] @ Wcomb^T + bcomb
        GP p0 = {x, WcombX, ginX, bcombX, TIN * BB, GG, PP, PP, GG, 0};
        GP p1 = {z, WcombZ, ginZ, bcombZ, TIN * BB, GG, PP, PP, GG, 0};
        dim3 g((TIN * BB + 127) / 128, GG / 128, 2);
        sgemm_k<A_XG, B_NK, E_BIAS><<<g, 256>>>(p0, p1);
    }

    // ---- encoder recurrence (t=0 needs no GEMM: h0 = 0) ----
    lstm_cell_k<<<4096, 256>>>(ginX, cX, cX, allh, 1);
    lstm_cell_k<<<4096, 256>>>(ginZ, cZ, cZ, allhz, 1);
    for (int t = 1; t < TIN; t++) {
        GP p0 = {allh  + (size_t)(t - 1) * BB * HH, enc_whh,  gates,
                 ginX + (size_t)t * BB * GG, BB, GG, HH, HH, GG, GG};
        GP p1 = {allhz + (size_t)(t - 1) * BB * HH, encp_whh, gates + (size_t)BB * GG,
                 ginZ + (size_t)t * BB * GG, BB, GG, HH, HH, GG, GG};
        dim3 g(BB / 128, GG / 128, 2);
        sgemm_k<A_PLAIN, B_NK, E_PRE><<<g, 256>>>(p0, p1);
        lstm_cell_k<<<4096, 256>>>(gates, cX, cX, allh + (size_t)t * BB * HH, 0);
        lstm_cell_k<<<4096, 256>>>(gates + (size_t)BB * GG, cZ, cZ, allhz + (size_t)t * BB * HH, 0);
    }

    // ---- decoder ----
    for (int t = 0; t < TOUT; t++) {
        const float* hprev = (t == 0) ? (allh + (size_t)(TIN - 1) * BB * HH)
                                      : (dechs + (size_t)(t - 1) * BB * HH);
        const float* cptr = (t == 0) ? cX : decc;
        attention_k<<<BB, 256>>>(allh, allhz, hprev, cptr, hcat);
        GP p0 = {hcat, Wcat, gates, bcat, BB, GG, 2048, 2048, GG, 0};
        dim3 g(BB / 128, GG / 128, 1);
        sgemm_k<A_PLAIN, B_NK, E_BIAS><<<g, 256>>>(p0, p0);
        lstm_cell_k<<<4096, 256>>>(gates, cptr, decc, dechs + (size_t)t * BB * HH, 0);
    }

    // ---- output projection: out[b,t,:] = dechs[t,b,:] @ pose_w^T + pose_b ----
    {
        GP p0 = {dechs, pose_w, out, pose_b, BB * TOUT, PP, HH, HH, PP, 0};
        dim3 g((BB * TOUT + 127) / 128, 1, 1);
        sgemm_k<A_PG, B_NK, E_BIAS><<<g, 256>>>(p0, p0);
    }
}

// round 3
// speedup vs baseline: 1.5170x; 1.5119x over previous
#include <cuda_runtime.h>
#include <mma.h>
#include <math.h>

using namespace nvcuda;

#define BB 1024
#define HH 1024
#define DD 512
#define PP 66
#define TIN 10
#define TOUT 25
#define GG 4096   // 4*HH

// ---------------- static device scratch (no allocations allowed) ----------------
__device__ float d_WcombX[GG * PP];
__device__ float d_WcombZ[GG * PP];
__device__ float d_bcombX[GG];
__device__ float d_bcombZ[GG];
__device__ float d_Wcat[(size_t)GG * 2048];          // [4096][2048]: cols 0..1023 = dec_whh, 1024..2047 = dec_wih@lin_w
__device__ float d_bcat[GG];
__device__ float d_ginX[(size_t)TIN * BB * GG];      // precomputed input gates (incl. all biases)
__device__ float d_ginZ[(size_t)TIN * BB * GG];
__device__ float d_allh[(size_t)TIN * BB * HH];
__device__ float d_allhz[(size_t)TIN * BB * HH];
__device__ float d_cX[BB * HH];
__device__ float d_cZ[BB * HH];
__device__ float d_decc[BB * HH];
__device__ float d_gates[(size_t)2 * BB * GG];
__device__ float d_hcat[(size_t)BB * 2048];          // [atth | h_n]
__device__ float d_dechs[(size_t)TOUT * BB * HH];

// ---------------- tf32 tensor-core GEMM ----------------
struct GP {
    const float* A;
    const float* Bm;
    float* C;
    const float* ep;     // bias [N] or preadd matrix [M,N]
    int M, N, K, lda, ldc, ldep;
};

enum { A_PLAIN = 0, A_XG = 1, A_PG = 2 };   // A gather modes
enum { B_NK = 0, B_KN = 1 };                // B layout: [N,K] (use B^T) or [K,N]
enum { E_NONE = 0, E_BIAS = 1, E_PRE = 2 }; // epilogue

#define LDA_S 36   // As[128][36]   (k-tile 32 + pad)
#define LDB_S 132  // Bs[32][132]   (n-tile 128 + pad)
#define LDC_S 132  // Cs[128][132]
#define SMEM_FLOATS (128 * LDC_S)            // 16896 floats = 67584 B (unions As+Bs)
#define SMEM_BYTES (SMEM_FLOATS * 4)

template <int AMAP, int BMODE, int EPI>
__global__ __launch_bounds__(256) void tgemm_k(GP p0, GP p1) {
    extern __shared__ float sm[];
    GP p = (blockIdx.z == 0) ? p0 : p1;
    float* As = sm;                 // 128*36 = 4608 floats
    float* Bs = sm + 128 * LDA_S;   // 32*132 = 4224 floats  (total 8832 < 16896)
    float* Cs = sm;                 // reused after mainloop

    const int tid = threadIdx.x;
    const int warp = tid >> 5;
    const int wm = warp & 1;        // warp tile: 64 (m) x 32 (n); 2x4 warp grid
    const int wn = warp >> 1;
    const int m0 = blockIdx.x * 128, n0 = blockIdx.y * 128;

    wmma::fragment<wmma::accumulator, 16, 16, 8, float> acc[4][2];
#pragma unroll
    for (int i = 0; i < 4; i++)
#pragma unroll
        for (int j = 0; j < 2; j++) wmma::fill_fragment(acc[i][j], 0.f);

    for (int k0 = 0; k0 < p.K; k0 += 32) {
        __syncthreads();
        // ---- load A tile: 128 x 32, coalesced along k ----
#pragma unroll
        for (int l = 0; l < 16; l++) {
            int idx = tid + 256 * l;
            int k = idx & 31, m = idx >> 5;
            int gm = m0 + m, gk = k0 + k;
            float v = 0.f;
            if (gm < p.M && gk < p.K) {
                size_t off;
                if (AMAP == A_PLAIN) {
                    off = (size_t)gm * p.lda + gk;
                } else if (AMAP == A_XG) {   // row (t*BB+b) -> x[b, t, k]
                    int t = gm / BB, b = gm % BB;
                    off = (size_t)b * (TIN * PP) + (size_t)t * PP + gk;
                } else {                     // row (b*TOUT+t) -> dechs[t, b, k]
                    int b = gm / TOUT, t = gm % TOUT;
                    off = (size_t)t * BB * HH + (size_t)b * HH + gk;
                }
                v = p.A[off];
            }
            As[m * LDA_S + k] = v;
        }
        // ---- load B tile: 32 x 128 into Bs[k][n] ----
        if (BMODE == B_NK) {
#pragma unroll
            for (int l = 0; l < 16; l++) {
                int idx = tid + 256 * l;
                int k = idx & 31, n = idx >> 5;   // coalesced along k in gmem
                int gn = n0 + n, gk = k0 + k;
                float v = 0.f;
                if (gn < p.N && gk < p.K) v = p.Bm[(size_t)gn * p.K + gk];
                Bs[k * LDB_S + n] = v;
            }
        } else {
#pragma unroll
            for (int l = 0; l < 16; l++) {
                int idx = tid + 256 * l;
                int n = idx & 127, k = idx >> 7;  // coalesced along n in gmem
                int gn = n0 + n, gk = k0 + k;
                float v = 0.f;
                if (gn < p.N && gk < p.K) v = p.Bm[(size_t)gk * p.N + gn];
                Bs[k * LDB_S + n] = v;
            }
        }
        __syncthreads();
        // ---- tensor-core compute: 4 k-steps of m16n16k8 tf32 ----
#pragma unroll
        for (int kk = 0; kk < 4; kk++) {
            wmma::fragment<wmma::matrix_a, 16, 16, 8, wmma::precision::tf32, wmma::row_major> af[4];
            wmma::fragment<wmma::matrix_b, 16, 16, 8, wmma::precision::tf32, wmma::row_major> bf[2];
#pragma unroll
            for (int i = 0; i < 4; i++) {
                wmma::load_matrix_sync(af[i], As + (wm * 64 + i * 16) * LDA_S + kk * 8, LDA_S);
#pragma unroll
                for (int t = 0; t < af[i].num_elements; t++)
                    af[i].x[t] = wmma::__float_to_tf32(af[i].x[t]);
            }
#pragma unroll
            for (int j = 0; j < 2; j++) {
                wmma::load_matrix_sync(bf[j], Bs + (kk * 8) * LDB_S + wn * 32 + j * 16, LDB_S);
#pragma unroll
                for (int t = 0; t < bf[j].num_elements; t++)
                    bf[j].x[t] = wmma::__float_to_tf32(bf[j].x[t]);
            }
#pragma unroll
            for (int i = 0; i < 4; i++)
#pragma unroll
                for (int j = 0; j < 2; j++)
                    wmma::mma_sync(acc[i][j], af[i], bf[j], acc[i][j]);
        }
    }

    // ---- stage accumulators through smem, then fused epilogue ----
    __syncthreads();
#pragma unroll
    for (int i = 0; i < 4; i++)
#pragma unroll
        for (int j = 0; j < 2; j++)
            wmma::store_matrix_sync(Cs + (wm * 64 + i * 16) * LDC_S + wn * 32 + j * 16,
                                    acc[i][j], LDC_S, wmma::mem_row_major);
    __syncthreads();
#pragma unroll
    for (int l = 0; l < 64; l++) {
        int idx = tid + 256 * l;
        int n = idx & 127, m = idx >> 7;
        int gm = m0 + m, gn = n0 + n;
        if (gm >= p.M || gn >= p.N) continue;
        float v = Cs[m * LDC_S + n];
        if (EPI == E_BIAS) v += p.ep[gn];
        if (EPI == E_PRE) v += p.ep[(size_t)gm * p.ldep + gn];
        p.C[(size_t)gm * p.ldc + gn] = v;
    }
}

// ---------------- LSTM pointwise cell ----------------
__global__ void lstm_cell_k(const float* __restrict__ gates, const float* __restrict__ cprev,
                            float* __restrict__ cout, float* __restrict__ hout, int first) {
    int idx = blockIdx.x * blockDim.x + threadIdx.x;
    if (idx >= BB * HH) return;
    int b = idx >> 10, u = idx & 1023;
    const float* g = gates + (size_t)b * GG;
    float gi = g[u], gf = g[HH + u], gc = g[2 * HH + u], go = g[3 * HH + u];
    float c = first ? 0.f : cprev[idx];
    float si = 1.f / (1.f + expf(-gi));
    float sf = 1.f / (1.f + expf(-gf));
    float so = 1.f / (1.f + expf(-go));
    float cn = sf * c + si * tanhf(gc);
    cout[idx] = cn;
    hout[idx] = so * tanhf(cn);
}

// ---------------- attention (one block per batch row) ----------------
__global__ void attention_k(const float* __restrict__ allh, const float* __restrict__ allhz,
                            const float* __restrict__ hprev, const float* __restrict__ cvec,
                            float* __restrict__ hcat) {
    int b = blockIdx.x;
    int tid = threadIdx.x, lane = tid & 31, w = tid >> 5;  // 8 warps
    __shared__ float sc[21];
    __shared__ float wts[21];
    const float* cb = cvec + (size_t)b * HH;

    for (int s = w; s < 21; s += 8) {
        const float* hs = (s < TIN)  ? (allh + ((size_t)s * BB + b) * HH)
                        : (s == TIN) ? (hprev + (size_t)b * HH)
                                     : (allhz + ((size_t)(s - TIN - 1) * BB + b) * HH);
        float part = 0.f;
        for (int u = lane; u < HH; u += 32) part += hs[u] * cb[u];
#pragma unroll
        for (int off = 16; off; off >>= 1) part += __shfl_down_sync(0xffffffffu, part, off);
        if (lane == 0) sc[s] = part;
    }
    __syncthreads();
    if (tid == 0) {
        float mx = sc[0];
        for (int s = 1; s < 21; s++) mx = fmaxf(mx, sc[s]);
        float sum = 0.f;
        for (int s = 0; s < 21; s++) { float e = expf(sc[s] - mx); wts[s] = e; sum += e; }
        float inv = 1.f / sum;
        for (int s = 0; s < 21; s++) wts[s] *= inv;
    }
    __syncthreads();
    float* out = hcat + (size_t)b * 2048;
    for (int u = tid; u < HH; u += blockDim.x) {
        float accv = 0.f;
#pragma unroll
        for (int s = 0; s < 21; s++) {
            const float* hs = (s < TIN)  ? (allh + ((size_t)s * BB + b) * HH)
                            : (s == TIN) ? (hprev + (size_t)b * HH)
                                         : (allhz + ((size_t)(s - TIN - 1) * BB + b) * HH);
            accv += wts[s] * hs[u];
        }
        out[u] = accv;                                   // new "h" into the cell = atth
        out[HH + u] = hprev[(size_t)b * HH + u];         // h_n for the folded lin path
    }
}

// ---------------- bias folding: out[j] = b1[j] + b2[j] + dot(wih[j,:], vec) ----------------
__global__ void prep_bias_k(const float* __restrict__ wih, const float* __restrict__ vec,
                            const float* __restrict__ b1, const float* __restrict__ b2,
                            float* __restrict__ out) {
    int wid = (blockIdx.x * blockDim.x + threadIdx.x) >> 5;
    int lane = threadIdx.x & 31;
    if (wid >= GG) return;
    const float* row = wih + (size_t)wid * DD;
    float s = 0.f;
    for (int d = lane; d < DD; d += 32) s += row[d] * vec[d];
#pragma unroll
    for (int off = 16; off; off >>= 1) s += __shfl_down_sync(0xffffffffu, s, off);
    if (lane == 0) out[wid] = b1[wid] + b2[wid] + s;
}

// copy dec_whh into left half of Wcat
__global__ void pack_wcat_k(const float* __restrict__ whh) {
    size_t idx = (size_t)blockIdx.x * blockDim.x + threadIdx.x;
    if (idx >= (size_t)GG * HH) return;
    size_t j = idx >> 10, m = idx & 1023;
    d_Wcat[j * 2048 + m] = whh[idx];
}

// ---------------- host orchestration ----------------
extern "C" void kernel_launch(void* const* d_in, const int* in_sizes, int n_in,
                              void* d_out, int out_size) {
    const float* x        = (const float*)d_in[0];
    const float* z        = (const float*)d_in[1];
    const float* wf       = (const float*)d_in[2];
    const float* bf       = (const float*)d_in[3];
    const float* enc_wih  = (const float*)d_in[4];
    const float* enc_whh  = (const float*)d_in[5];
    const float* enc_bih  = (const float*)d_in[6];
    const float* enc_bhh  = (const float*)d_in[7];
    const float* encp_wih = (const float*)d_in[8];
    const float* encp_whh = (const float*)d_in[9];
    const float* encp_bih = (const float*)d_in[10];
    const float* encp_bhh = (const float*)d_in[11];
    const float* dec_wih  = (const float*)d_in[12];
    const float* dec_whh  = (const float*)d_in[13];
    const float* dec_bih  = (const float*)d_in[14];
    const float* dec_bhh  = (const float*)d_in[15];
    const float* lin_w    = (const float*)d_in[16];
    const float* lin_b    = (const float*)d_in[17];
    const float* pose_w   = (const float*)d_in[18];
    const float* pose_b   = (const float*)d_in[19];
    float* out = (float*)d_out;

    void* pv;
    cudaGetSymbolAddress(&pv, d_WcombX); float* WcombX = (float*)pv;
    cudaGetSymbolAddress(&pv, d_WcombZ); float* WcombZ = (float*)pv;
    cudaGetSymbolAddress(&pv, d_bcombX); float* bcombX = (float*)pv;
    cudaGetSymbolAddress(&pv, d_bcombZ); float* bcombZ = (float*)pv;
    cudaGetSymbolAddress(&pv, d_Wcat);   float* Wcat   = (float*)pv;
    cudaGetSymbolAddress(&pv, d_bcat);   float* bcat   = (float*)pv;
    cudaGetSymbolAddress(&pv, d_ginX);   float* ginX   = (float*)pv;
    cudaGetSymbolAddress(&pv, d_ginZ);   float* ginZ   = (float*)pv;
    cudaGetSymbolAddress(&pv, d_allh);   float* allh   = (float*)pv;
    cudaGetSymbolAddress(&pv, d_allhz);  float* allhz  = (float*)pv;
    cudaGetSymbolAddress(&pv, d_cX);     float* cX     = (float*)pv;
    cudaGetSymbolAddress(&pv, d_cZ);     float* cZ     = (float*)pv;
    cudaGetSymbolAddress(&pv, d_decc);   float* decc   = (float*)pv;
    cudaGetSymbolAddress(&pv, d_gates);  float* gates  = (float*)pv;
    cudaGetSymbolAddress(&pv, d_hcat);   float* hcat   = (float*)pv;
    cudaGetSymbolAddress(&pv, d_dechs);  float* dechs  = (float*)pv;

    // opt-in dynamic smem > 48KB for every instantiation we launch
    cudaFuncSetAttribute(tgemm_k<A_PLAIN, B_KN, E_NONE>, cudaFuncAttributeMaxDynamicSharedMemorySize, SMEM_BYTES);
    cudaFuncSetAttribute(tgemm_k<A_XG,    B_NK, E_BIAS>, cudaFuncAttributeMaxDynamicSharedMemorySize, SMEM_BYTES);
    cudaFuncSetAttribute(tgemm_k<A_PLAIN, B_NK, E_PRE>,  cudaFuncAttributeMaxDynamicSharedMemorySize, SMEM_BYTES);
    cudaFuncSetAttribute(tgemm_k<A_PLAIN, B_NK, E_BIAS>, cudaFuncAttributeMaxDynamicSharedMemorySize, SMEM_BYTES);
    cudaFuncSetAttribute(tgemm_k<A_PG,    B_NK, E_BIAS>, cudaFuncAttributeMaxDynamicSharedMemorySize, SMEM_BYTES);

    // ---- one-time folds (cheap, fully parallel) ----
    pack_wcat_k<<<(GG * HH + 255) / 256, 256>>>(dec_whh);
    prep_bias_k<<<512, 256>>>(enc_wih, bf, enc_bih, enc_bhh, bcombX);
    prep_bias_k<<<512, 256>>>(encp_wih, bf, encp_bih, encp_bhh, bcombZ);
    prep_bias_k<<<512, 256>>>(dec_wih, lin_b, dec_bih, dec_bhh, bcat);

    {   // Wcomb = enc_wih @ wf  (both encoders via z)
        GP p0 = {enc_wih,  wf, WcombX, nullptr, GG, PP, DD, DD, PP, 0};
        GP p1 = {encp_wih, wf, WcombZ, nullptr, GG, PP, DD, DD, PP, 0};
        dim3 g((GG + 127) / 128, 1, 2);
        tgemm_k<A_PLAIN, B_KN, E_NONE><<<g, 256, SMEM_BYTES>>>(p0, p1);
    }
    {   // Weff = dec_wih @ lin_w into right half of Wcat
        GP p0 = {dec_wih, lin_w, Wcat + 1024, nullptr, GG, HH, DD, DD, 2048, 0};
        dim3 g((GG + 127) / 128, (HH + 127) / 128, 1);
        tgemm_k<A_PLAIN, B_KN, E_NONE><<<g, 256, SMEM_BYTES>>>(p0, p0);
    }
    {   // input gates for all timesteps: gin[t,b,:] = x[b,t,:] @ Wcomb^T + bcomb
        GP p0 = {x, WcombX, ginX, bcombX, TIN * BB, GG, PP, PP, GG, 0};
        GP p1 = {z, WcombZ, ginZ, bcombZ, TIN * BB, GG, PP, PP, GG, 0};
        dim3 g((TIN * BB + 127) / 128, GG / 128, 2);
        tgemm_k<A_XG, B_NK, E_BIAS><<<g, 256, SMEM_BYTES>>>(p0, p1);
    }

    // ---- encoder recurrence (t=0 needs no GEMM: h0 = 0) ----
    lstm_cell_k<<<4096, 256>>>(ginX, cX, cX, allh, 1);
    lstm_cell_k<<<4096, 256>>>(ginZ, cZ, cZ, allhz, 1);
    for (int t = 1; t < TIN; t++) {
        GP p0 = {allh  + (size_t)(t - 1) * BB * HH, enc_whh,  gates,
                 ginX + (size_t)t * BB * GG, BB, GG, HH, HH, GG, GG};
        GP p1 = {allhz + (size_t)(t - 1) * BB * HH, encp_whh, gates + (size_t)BB * GG,
                 ginZ + (size_t)t * BB * GG, BB, GG, HH, HH, GG, GG};
        dim3 g(BB / 128, GG / 128, 2);
        tgemm_k<A_PLAIN, B_NK, E_PRE><<<g, 256, SMEM_BYTES>>>(p0, p1);
        lstm_cell_k<<<4096, 256>>>(gates, cX, cX, allh + (size_t)t * BB * HH, 0);
        lstm_cell_k<<<4096, 256>>>(gates + (size_t)BB * GG, cZ, cZ, allhz + (size_t)t * BB * HH, 0);
    }

    // ---- decoder ----
    for (int t = 0; t < TOUT; t++) {
        const float* hprev = (t == 0) ? (allh + (size_t)(TIN - 1) * BB * HH)
                                      : (dechs + (size_t)(t - 1) * BB * HH);
        const float* cptr = (t == 0) ? cX : decc;
        attention_k<<<BB, 256>>>(allh, allhz, hprev, cptr, hcat);
        GP p0 = {hcat, Wcat, gates, bcat, BB, GG, 2048, 2048, GG, 0};
        dim3 g(BB / 128, GG / 128, 1);
        tgemm_k<A_PLAIN, B_NK, E_BIAS><<<g, 256, SMEM_BYTES>>>(p0, p0);
        lstm_cell_k<<<4096, 256>>>(gates, cptr, decc, dechs + (size_t)t * BB * HH, 0);
    }

    // ---- output projection: out[b,t,:] = dechs[t,b,:] @ pose_w^T + pose_b ----
    {
        GP p0 = {dechs, pose_w, out, pose_b, BB * TOUT, PP, HH, HH, PP, 0};
        dim3 g((BB * TOUT + 127) / 128, 1, 1);
        tgemm_k<A_PG, B_NK, E_BIAS><<<g, 256, SMEM_BYTES>>>(p0, p0);
    }
}

// round 4
// speedup vs baseline: 2.5316x; 1.6688x over previous
#include <cuda_runtime.h>
#include <mma.h>
#include <math.h>

using namespace nvcuda;

#define BB 1024
#define HH 1024
#define DD 512
#define PP 66
#define TIN 10
#define TOUT 25
#define GG 4096   // 4*HH

// ---------------- static device scratch (no allocations allowed) ----------------
__device__ float d_WcombX[(size_t)GG * 256];         // padded to 256 cols
__device__ float d_WcombZ[(size_t)GG * 256];
__device__ float d_bcombX[GG];
__device__ float d_bcombZ[GG];
__device__ float d_Wcat[(size_t)GG * 2048];          // cols 0..1023 = dec_whh, 1024..2047 = dec_wih@lin_w
__device__ float d_bcat[GG];
__device__ float d_ginX[(size_t)TIN * BB * GG];
__device__ float d_ginZ[(size_t)TIN * BB * GG];
__device__ float d_allh[(size_t)TIN * BB * HH];
__device__ float d_allhz[(size_t)TIN * BB * HH];
__device__ float d_cX[BB * HH];
__device__ float d_cZ[BB * HH];
__device__ float d_decc[BB * HH];
__device__ float d_gates[(size_t)2 * BB * GG];
__device__ float d_hcat[(size_t)BB * 2048];          // [atth | h_n]
__device__ float d_dechs[(size_t)TOUT * BB * HH];
__device__ float d_poseC[(size_t)TOUT * BB * 256];   // padded pose GEMM output

// ---------------- pipelined tf32 tensor-core GEMM (128x256 tile, cp.async) ----------------
struct GP {
    const float* A;
    const float* Bm;
    float* C;
    int M, N, K, lda, ldb, ldc;
};

enum { A_PLAIN = 0, A_XG = 1 };          // A gather: plain rows, or x[b,t,k] gather
enum { B_NK = 0, B_KN = 1 };             // B layout: [N,K] (use B^T) or [K,N]

#define ST_A 4608        // floats: As[128][36]
#define ST_B 9216        // floats: max(Bnk[256][36]=9216, Bkn[32][260]=8320)
#define ST_STAGE (ST_A + ST_B)
#define HSMEM_BYTES (2 * ST_STAGE * 4)   // 110592 B

__device__ __forceinline__ unsigned sptr(const void* p) {
    return (unsigned)__cvta_generic_to_shared(p);
}
__device__ __forceinline__ void cpa16(unsigned d, const void* s, bool pr) {
    int sz = pr ? 16 : 0;
    asm volatile("cp.async.cg.shared.global [%0], [%1], 16, %2;\n" :: "r"(d), "l"(s), "r"(sz));
}
__device__ __forceinline__ void cpa4(unsigned d, const void* s, bool pr) {
    int sz = pr ? 4 : 0;
    asm volatile("cp.async.ca.shared.global [%0], [%1], 4, %2;\n" :: "r"(d), "l"(s), "r"(sz));
}

template <int AMAP, int BMODE, bool ALA, bool ALB>
__global__ __launch_bounds__(256) void hgemm_k(GP p0, GP p1) {
    extern __shared__ float sm[];
    GP p = (blockIdx.z == 0) ? p0 : p1;
    const int tid = threadIdx.x;
    const int warp = tid >> 5;
    const int wm = warp & 1;       // 2 x 4 warp grid, warp tile 64m x 64n
    const int wn = warp >> 1;
    const int m0 = blockIdx.x * 128, n0 = blockIdx.y * 256;
    const int KT = (p.K + 31) >> 5;

    wmma::fragment<wmma::accumulator, 16, 16, 8, float> acc[4][4];
#pragma unroll
    for (int i = 0; i < 4; i++)
#pragma unroll
        for (int j = 0; j < 4; j++) wmma::fill_fragment(acc[i][j], 0.f);

    auto loadTile = [&](int kt, int stg) {
        float* As = sm + stg * ST_STAGE;
        float* Bs = As + ST_A;
        const int k0 = kt << 5;
        // ---- A: 128 x 32 into As[m][k] (ld 36) ----
        if (ALA) {
#pragma unroll
            for (int i = 0; i < 4; i++) {
                int c = tid + 256 * i;
                int m = c >> 3, kq = c & 7;
                int gm = m0 + m, gk = k0 + kq * 4;
                bool pr = (gm < p.M) && (gk < p.K);
                const float* src = pr ? (p.A + (size_t)gm * p.lda + gk) : p.A;
                cpa16(sptr(As + m * 36 + kq * 4), src, pr);
            }
        } else {
#pragma unroll
            for (int i = 0; i < 16; i++) {
                int idx = tid + 256 * i;
                int m = idx >> 5, k = idx & 31;
                int gm = m0 + m, gk = k0 + k;
                bool pr = (gm < p.M) && (gk < p.K);
                const float* src = p.A;
                if (pr) {
                    size_t off;
                    if (AMAP == A_XG) { int t = gm / BB, b = gm % BB; off = (size_t)b * (TIN * PP) + (size_t)t * PP + gk; }
                    else off = (size_t)gm * p.lda + gk;
                    src = p.A + off;
                }
                cpa4(sptr(As + m * 36 + k), src, pr);
            }
        }
        // ---- B ----
        if (BMODE == B_NK) {       // Bs[n][k] (ld 36), fragments col_major
            if (ALB) {
#pragma unroll
                for (int i = 0; i < 8; i++) {
                    int c = tid + 256 * i;
                    int n = c >> 3, kq = c & 7;
                    int gn = n0 + n, gk = k0 + kq * 4;
                    bool pr = (gn < p.N) && (gk < p.K);
                    const float* src = pr ? (p.Bm + (size_t)gn * p.ldb + gk) : p.Bm;
                    cpa16(sptr(Bs + n * 36 + kq * 4), src, pr);
                }
            } else {
#pragma unroll
                for (int i = 0; i < 32; i++) {
                    int idx = tid + 256 * i;
                    int n = idx >> 5, k = idx & 31;
                    int gn = n0 + n, gk = k0 + k;
                    bool pr = (gn < p.N) && (gk < p.K);
                    const float* src = pr ? (p.Bm + (size_t)gn * p.ldb + gk) : p.Bm;
                    cpa4(sptr(Bs + n * 36 + k), src, pr);
                }
            }
        } else {                    // Bs[k][n] (ld 260), fragments row_major
            if (ALB) {
#pragma unroll
                for (int i = 0; i < 8; i++) {
                    int c = tid + 256 * i;
                    int k = c >> 6, nq = c & 63;
                    int gk = k0 + k, gn = n0 + nq * 4;
                    bool pr = (gk < p.K) && (gn < p.N);
                    const float* src = pr ? (p.Bm + (size_t)gk * p.ldb + gn) : p.Bm;
                    cpa16(sptr(Bs + k * 260 + nq * 4), src, pr);
                }
            } else {
#pragma unroll
                for (int i = 0; i < 32; i++) {
                    int idx = tid + 256 * i;
                    int k = idx >> 8, n = idx & 255;
                    int gk = k0 + k, gn = n0 + n;
                    bool pr = (gk < p.K) && (gn < p.N);
                    const float* src = pr ? (p.Bm + (size_t)gk * p.ldb + gn) : p.Bm;
                    cpa4(sptr(Bs + k * 260 + n), src, pr);
                }
            }
        }
    };

    loadTile(0, 0);
    asm volatile("cp.async.commit_group;\n");

    for (int kt = 0; kt < KT; kt++) {
        int stg = kt & 1;
        if (kt + 1 < KT) {
            loadTile(kt + 1, (kt + 1) & 1);
            asm volatile("cp.async.commit_group;\n");
            asm volatile("cp.async.wait_group 1;\n");
        } else {
            asm volatile("cp.async.wait_group 0;\n");
        }
        __syncthreads();
        float* As = sm + stg * ST_STAGE;
        float* Bs = As + ST_A;
#pragma unroll
        for (int kk = 0; kk < 4; kk++) {
            wmma::fragment<wmma::matrix_a, 16, 16, 8, wmma::precision::tf32, wmma::row_major> af[4];
#pragma unroll
            for (int i = 0; i < 4; i++)
                wmma::load_matrix_sync(af[i], As + (wm * 64 + i * 16) * 36 + kk * 8, 36);
            if (BMODE == B_NK) {
                wmma::fragment<wmma::matrix_b, 16, 16, 8, wmma::precision::tf32, wmma::col_major> bf[4];
#pragma unroll
                for (int j = 0; j < 4; j++)
                    wmma::load_matrix_sync(bf[j], Bs + (wn * 64 + j * 16) * 36 + kk * 8, 36);
#pragma unroll
                for (int i = 0; i < 4; i++)
#pragma unroll
                    for (int j = 0; j < 4; j++)
                        wmma::mma_sync(acc[i][j], af[i], bf[j], acc[i][j]);
            } else {
                wmma::fragment<wmma::matrix_b, 16, 16, 8, wmma::precision::tf32, wmma::row_major> bf[4];
#pragma unroll
                for (int j = 0; j < 4; j++)
                    wmma::load_matrix_sync(bf[j], Bs + (kk * 8) * 260 + wn * 64 + j * 16, 260);
#pragma unroll
                for (int i = 0; i < 4; i++)
#pragma unroll
                    for (int j = 0; j < 4; j++)
                        wmma::mma_sync(acc[i][j], af[i], bf[j], acc[i][j]);
            }
        }
        __syncthreads();
    }

    // direct fragment -> gmem store (all launches guarantee in-bounds tiles)
#pragma unroll
    for (int i = 0; i < 4; i++)
#pragma unroll
        for (int j = 0; j < 4; j++)
            wmma::store_matrix_sync(p.C + (size_t)(m0 + wm * 64 + i * 16) * p.ldc + n0 + wn * 64 + j * 16,
                                    acc[i][j], p.ldc, wmma::mem_row_major);
}

// ---------------- fused LSTM pointwise cell (adds pre-gates and/or bias) ----------------
struct CP {
    const float* mm;     // raw h@W^T gates [B,4H]
    const float* pre;    // optional pre-add [B,4H] (gin_t)
    const float* bias;   // optional bias [4H]
    const float* cprev;
    float* cout;
    float* hout;
};

__global__ void lstm_cell_k(CP pa, CP pb, int first) {
    CP p = blockIdx.y ? pb : pa;
    int idx = blockIdx.x * blockDim.x + threadIdx.x;
    if (idx >= BB * HH) return;
    int b = idx >> 10, u = idx & 1023;
    const float* g = p.mm + (size_t)b * GG;
    float gi = g[u], gf = g[HH + u], gc = g[2 * HH + u], go = g[3 * HH + u];
    if (p.pre) {
        const float* q = p.pre + (size_t)b * GG;
        gi += q[u]; gf += q[HH + u]; gc += q[2 * HH + u]; go += q[3 * HH + u];
    }
    if (p.bias) {
        gi += p.bias[u]; gf += p.bias[HH + u]; gc += p.bias[2 * HH + u]; go += p.bias[3 * HH + u];
    }
    float c = first ? 0.f : p.cprev[idx];
    float si = 1.f / (1.f + expf(-gi));
    float sf = 1.f / (1.f + expf(-gf));
    float so = 1.f / (1.f + expf(-go));
    float cn = sf * c + si * tanhf(gc);
    p.cout[idx] = cn;
    p.hout[idx] = so * tanhf(cn);
}

// ---------------- attention (one block per batch row) ----------------
__global__ void attention_k(const float* __restrict__ allh, const float* __restrict__ allhz,
                            const float* __restrict__ hprev, const float* __restrict__ cvec,
                            float* __restrict__ hcat) {
    int b = blockIdx.x;
    int tid = threadIdx.x, lane = tid & 31, w = tid >> 5;  // 8 warps
    __shared__ float sc[21];
    __shared__ float wts[21];
    const float* cb = cvec + (size_t)b * HH;

    for (int s = w; s < 21; s += 8) {
        const float* hs = (s < TIN)  ? (allh + ((size_t)s * BB + b) * HH)
                        : (s == TIN) ? (hprev + (size_t)b * HH)
                                     : (allhz + ((size_t)(s - TIN - 1) * BB + b) * HH);
        float part = 0.f;
        for (int u = lane; u < HH; u += 32) part += hs[u] * cb[u];
#pragma unroll
        for (int off = 16; off; off >>= 1) part += __shfl_down_sync(0xffffffffu, part, off);
        if (lane == 0) sc[s] = part;
    }
    __syncthreads();
    if (tid == 0) {
        float mx = sc[0];
        for (int s = 1; s < 21; s++) mx = fmaxf(mx, sc[s]);
        float sum = 0.f;
        for (int s = 0; s < 21; s++) { float e = expf(sc[s] - mx); wts[s] = e; sum += e; }
        float inv = 1.f / sum;
        for (int s = 0; s < 21; s++) wts[s] *= inv;
    }
    __syncthreads();
    float* out = hcat + (size_t)b * 2048;
    for (int u = tid; u < HH; u += blockDim.x) {
        float accv = 0.f;
#pragma unroll
        for (int s = 0; s < 21; s++) {
            const float* hs = (s < TIN)  ? (allh + ((size_t)s * BB + b) * HH)
                            : (s == TIN) ? (hprev + (size_t)b * HH)
                                         : (allhz + ((size_t)(s - TIN - 1) * BB + b) * HH);
            accv += wts[s] * hs[u];
        }
        out[u] = accv;
        out[HH + u] = hprev[(size_t)b * HH + u];
    }
}

// ---------------- bias folding: out[j] = b1[j] + b2[j] + dot(wih[j,:], vec) ----------------
__global__ void prep_bias_k(const float* __restrict__ wih, const float* __restrict__ vec,
                            const float* __restrict__ b1, const float* __restrict__ b2,
                            float* __restrict__ out) {
    int wid = (blockIdx.x * blockDim.x + threadIdx.x) >> 5;
    int lane = threadIdx.x & 31;
    if (wid >= GG) return;
    const float* row = wih + (size_t)wid * DD;
    float s = 0.f;
    for (int d = lane; d < DD; d += 32) s += row[d] * vec[d];
#pragma unroll
    for (int off = 16; off; off >>= 1) s += __shfl_down_sync(0xffffffffu, s, off);
    if (lane == 0) out[wid] = b1[wid] + b2[wid] + s;
}

// copy dec_whh into left half of Wcat
__global__ void pack_wcat_k(const float* __restrict__ whh) {
    size_t idx = (size_t)blockIdx.x * blockDim.x + threadIdx.x;
    if (idx >= (size_t)GG * HH) return;
    size_t j = idx >> 10, m = idx & 1023;
    d_Wcat[j * 2048 + m] = whh[idx];
}

// pose epilogue: out[b,t,p] = poseC[(t*BB+b)*256 + p] + pose_b[p]
__global__ void pose_fin_k(const float* __restrict__ pc, const float* __restrict__ pb,
                           float* __restrict__ out) {
    int idx = blockIdx.x * blockDim.x + threadIdx.x;
    if (idx >= BB * TOUT * PP) return;
    int pp = idx % PP;
    int bt = idx / PP;
    int t = bt % TOUT, b = bt / TOUT;
    out[idx] = pc[((size_t)t * BB + b) * 256 + pp] + pb[pp];
}

// ---------------- host orchestration ----------------
extern "C" void kernel_launch(void* const* d_in, const int* in_sizes, int n_in,
                              void* d_out, int out_size) {
    const float* x        = (const float*)d_in[0];
    const float* z        = (const float*)d_in[1];
    const float* wf       = (const float*)d_in[2];
    const float* bf       = (const float*)d_in[3];
    const float* enc_wih  = (const float*)d_in[4];
    const float* enc_whh  = (const float*)d_in[5];
    const float* enc_bih  = (const float*)d_in[6];
    const float* enc_bhh  = (const float*)d_in[7];
    const float* encp_wih = (const float*)d_in[8];
    const float* encp_whh = (const float*)d_in[9];
    const float* encp_bih = (const float*)d_in[10];
    const float* encp_bhh = (const float*)d_in[11];
    const float* dec_wih  = (const float*)d_in[12];
    const float* dec_whh  = (const float*)d_in[13];
    const float* dec_bih  = (const float*)d_in[14];
    const float* dec_bhh  = (const float*)d_in[15];
    const float* lin_w    = (const float*)d_in[16];
    const float* lin_b    = (const float*)d_in[17];
    const float* pose_w   = (const float*)d_in[18];
    const float* pose_b   = (const float*)d_in[19];
    float* out = (float*)d_out;

    void* pv;
    cudaGetSymbolAddress(&pv, d_WcombX); float* WcombX = (float*)pv;
    cudaGetSymbolAddress(&pv, d_WcombZ); float* WcombZ = (float*)pv;
    cudaGetSymbolAddress(&pv, d_bcombX); float* bcombX = (float*)pv;
    cudaGetSymbolAddress(&pv, d_bcombZ); float* bcombZ = (float*)pv;
    cudaGetSymbolAddress(&pv, d_Wcat);   float* Wcat   = (float*)pv;
    cudaGetSymbolAddress(&pv, d_bcat);   float* bcat   = (float*)pv;
    cudaGetSymbolAddress(&pv, d_ginX);   float* ginX   = (float*)pv;
    cudaGetSymbolAddress(&pv, d_ginZ);   float* ginZ   = (float*)pv;
    cudaGetSymbolAddress(&pv, d_allh);   float* allh   = (float*)pv;
    cudaGetSymbolAddress(&pv, d_allhz);  float* allhz  = (float*)pv;
    cudaGetSymbolAddress(&pv, d_cX);     float* cX     = (float*)pv;
    cudaGetSymbolAddress(&pv, d_cZ);     float* cZ     = (float*)pv;
    cudaGetSymbolAddress(&pv, d_decc);   float* decc   = (float*)pv;
    cudaGetSymbolAddress(&pv, d_gates);  float* gates  = (float*)pv;
    cudaGetSymbolAddress(&pv, d_hcat);   float* hcat   = (float*)pv;
    cudaGetSymbolAddress(&pv, d_dechs);  float* dechs  = (float*)pv;
    cudaGetSymbolAddress(&pv, d_poseC);  float* poseC  = (float*)pv;

    cudaFuncSetAttribute(hgemm_k<A_PLAIN, B_KN, true, false>, cudaFuncAttributeMaxDynamicSharedMemorySize, HSMEM_BYTES);
    cudaFuncSetAttribute(hgemm_k<A_XG,    B_NK, false, true>, cudaFuncAttributeMaxDynamicSharedMemorySize, HSMEM_BYTES);
    cudaFuncSetAttribute(hgemm_k<A_PLAIN, B_KN, true, true>,  cudaFuncAttributeMaxDynamicSharedMemorySize, HSMEM_BYTES);
    cudaFuncSetAttribute(hgemm_k<A_PLAIN, B_NK, true, true>,  cudaFuncAttributeMaxDynamicSharedMemorySize, HSMEM_BYTES);

    CP nil = {};

    // ---- one-time folds ----
    pack_wcat_k<<<(GG * HH + 255) / 256, 256>>>(dec_whh);
    prep_bias_k<<<512, 256>>>(enc_wih, bf, enc_bih, enc_bhh, bcombX);
    prep_bias_k<<<512, 256>>>(encp_wih, bf, encp_bih, encp_bhh, bcombZ);
    prep_bias_k<<<512, 256>>>(dec_wih, lin_b, dec_bih, dec_bhh, bcat);

    {   // Wcomb = enc_wih @ wf   [4096 x 66] into padded [4096 x 256]
        GP p0 = {enc_wih,  wf, WcombX, GG, PP, DD, DD, PP, 256};
        GP p1 = {encp_wih, wf, WcombZ, GG, PP, DD, DD, PP, 256};
        dim3 g(GG / 128, 1, 2);
        hgemm_k<A_PLAIN, B_KN, true, false><<<g, 256, HSMEM_BYTES>>>(p0, p1);
    }
    {   // Weff = dec_wih @ lin_w into right half of Wcat
        GP p0 = {dec_wih, lin_w, Wcat + 1024, GG, HH, DD, DD, HH, 2048};
        dim3 g(GG / 128, HH / 256, 1);
        hgemm_k<A_PLAIN, B_KN, true, true><<<g, 256, HSMEM_BYTES>>>(p0, p0);
    }
    {   // gin[t*B+b, :] = x[b,t,:] @ Wcomb^T  (bias added in cell via bcomb? no: bcomb folded here through pre path below)
        GP p0 = {x, WcombX, ginX, TIN * BB, GG, PP, PP, 256, GG};
        GP p1 = {z, WcombZ, ginZ, TIN * BB, GG, PP, PP, 256, GG};
        dim3 g(TIN * BB / 128, GG / 256, 2);
        hgemm_k<A_XG, B_NK, false, true><<<g, 256, HSMEM_BYTES>>>(p0, p1);
    }

    // ---- encoder recurrence (t=0: gates = gin + bcomb, h0=c0=0) ----
    {
        CP pa = {ginX, nullptr, bcombX, nullptr, cX, allh};
        CP pb = {ginZ, nullptr, bcombZ, nullptr, cZ, allhz};
        lstm_cell_k<<<dim3(4096, 2), 256>>>(pa, pb, 1);
    }
    for (int t = 1; t < TIN; t++) {
        GP p0 = {allh  + (size_t)(t - 1) * BB * HH, enc_whh,  gates,                    BB, GG, HH, HH, HH, GG};
        GP p1 = {allhz + (size_t)(t - 1) * BB * HH, encp_whh, gates + (size_t)BB * GG,  BB, GG, HH, HH, HH, GG};
        dim3 g(BB / 128, GG / 256, 2);
        hgemm_k<A_PLAIN, B_NK, true, true><<<g, 256, HSMEM_BYTES>>>(p0, p1);
        CP pa = {gates,                   ginX + (size_t)t * BB * GG, bcombX, cX, cX, allh  + (size_t)t * BB * HH};
        CP pb = {gates + (size_t)BB * GG, ginZ + (size_t)t * BB * GG, bcombZ, cZ, cZ, allhz + (size_t)t * BB * HH};
        lstm_cell_k<<<dim3(4096, 2), 256>>>(pa, pb, 0);
    }

    // ---- decoder ----
    for (int t = 0; t < TOUT; t++) {
        const float* hprev = (t == 0) ? (allh + (size_t)(TIN - 1) * BB * HH)
                                      : (dechs + (size_t)(t - 1) * BB * HH);
        const float* cptr = (t == 0) ? cX : decc;
        attention_k<<<BB, 256>>>(allh, allhz, hprev, cptr, hcat);
        GP p0 = {hcat, Wcat, gates, BB, GG, 2048, 2048, 2048, GG};
        dim3 g(BB / 128, GG / 256, 1);
        hgemm_k<A_PLAIN, B_NK, true, true><<<g, 256, HSMEM_BYTES>>>(p0, p0);
        CP pa = {gates, nullptr, bcat, cptr, decc, dechs + (size_t)t * BB * HH};
        lstm_cell_k<<<dim3(4096, 1), 256>>>(pa, pa, 0);
    }

    // ---- output projection into padded scratch, then bias+permute ----
    {
        GP p0 = {dechs, pose_w, poseC, TOUT * BB, PP, HH, HH, HH, 256};
        dim3 g(TOUT * BB / 128, 1, 1);
        hgemm_k<A_PLAIN, B_NK, true, true><<<g, 256, HSMEM_BYTES>>>(p0, p0);
        pose_fin_k<<<(BB * TOUT * PP + 255) / 256, 256>>>(poseC, pose_b, out);
    }
}